// round 14
// baseline (speedup 1.0000x reference)
#include <cuda_runtime.h>
#include <cuda_fp16.h>
#include <cstdint>

// Conv2d 3x3 s1 p1: x[32,64,56,56] * w[128,64,3,3] -> out[32,128,56,56]
// FP16 implicit GEMM (fp32 accum), mma.sync m16n8k16. 64x64 warp tile.
// B halo staged once per CTA (368 slots, stride 160B, channel-permuted so
// b0||b1 load as one conflict-free LDS.64). A taps cp.async triple-buffered.
// 2 CTAs/SM.

#define B_    32
#define CIN   64
#define COUT  128
#define HW    56
#define PADW  58
#define IMG   (HW*HW)             // 3136
#define NPIX  (B_*IMG)            // 100352
#define NT    128                 // pixels per CTA
#define NCTA  (NPIX/NT)           // 784
#define BSTRB 160                 // bytes per halo slot row (128B data + pad)
#define NSLOT 368                 // staged halo slot rows (max read slot = 367)
#define NTHR  128
#define PTHR  256                 // prep threads
#define TGRID (PADW*B_)           // 1856 transpose blocks

__device__ __half g_xpad[(size_t)B_*PADW*PADW*CIN];  // fp16 NHWC padded, channel-permuted
__device__ __half g_wt2[9*COUT*CIN];                 // fragment-major fp16 weights

#define XPAD_HALVES ((size_t)B_*PADW*PADW*CIN)

static __device__ __forceinline__ void mma16(float* d, const uint32_t* a,
                                             uint32_t b0, uint32_t b1) {
    asm volatile("mma.sync.aligned.m16n8k16.row.col.f32.f16.f16.f32 "
                 "{%0,%1,%2,%3}, {%4,%5,%6,%7}, {%8,%9}, {%0,%1,%2,%3};"
                 : "+f"(d[0]), "+f"(d[1]), "+f"(d[2]), "+f"(d[3])
                 : "r"(a[0]), "r"(a[1]), "r"(a[2]), "r"(a[3]), "r"(b0), "r"(b1));
}
static __device__ __forceinline__ void cp16(uint32_t saddr, const void* g) {
    asm volatile("cp.async.cg.shared.global [%0], [%1], 16;" :: "r"(saddr), "l"(g));
}
#define CP_COMMIT() asm volatile("cp.async.commit_group;" ::: "memory")
#define CP_WAIT(n)  asm volatile("cp.async.wait_group %0;" :: "n"(n) : "memory")

// channel permutation: slot position p holds channel pi(p)
static __device__ __forceinline__ int chan_pi(int p) {
    int s = p >> 4, r = p & 15, tig = r >> 2, j = r & 3;
    return s * 16 + 2 * tig + (j & 1) + ((j >> 1) & 1) * 8;
}

// ---------------- fused prep kernel ----------------
__global__ void k_prep(const float* __restrict__ x, const float* __restrict__ w) {
    const int bid = blockIdx.x, t = threadIdx.x;
    if (bid < TGRID) {
        int yp = bid % PADW, b = bid / PADW;
        __half* dst = g_xpad + ((size_t)b * PADW + yp) * PADW * CIN;
        if (yp == 0 || yp == PADW - 1) {
            for (int i = t; i < PADW * CIN; i += PTHR) dst[i] = __float2half(0.f);
            return;
        }
        __shared__ float s[CIN][HW + 1];
        int y = yp - 1;
        for (int i = t; i < CIN * HW; i += PTHR) {
            int c = i / HW, xx = i % HW;
            s[c][xx] = x[(((size_t)b * CIN + c) * HW + y) * HW + xx];
        }
        __syncthreads();
        if (t < 2 * CIN) {               // zero left/right halo columns
            int side = t >> 6, c = t & 63;
            dst[(side ? (PADW - 1) * CIN : 0) + c] = __float2half(0.f);
        }
        for (int i = t; i < HW * CIN; i += PTHR) {
            int px = i / CIN, pos = i % CIN;
            dst[(px + 1) * CIN + pos] = __float2half_rn(s[chan_pi(pos)][px]);
        }
    } else {
        // per kidx: [s(4)][atom(8)][lane(32)][j(8 halves)] = 8192 halves
        // (A-side channel mapping unchanged: contraction order is preserved,
        //  only B's storage order is permuted.)
        int i = (bid - TGRID) * PTHR + t;
        if (i >= 9 * COUT * CIN) return;
        int kidx = i / 8192;
        int e    = i % 8192;
        int s    = e / 2048;
        int atom = (e / 256) & 7;
        int lane = (e >> 3) & 31;
        int j    = e & 7;
        int oc = atom * 16 + (lane >> 2) + ((j >> 1) & 1) * 8;
        int c  = s * 16 + 2 * (lane & 3) + (j & 1) + ((j >> 2) & 1) * 8;
        g_wt2[i] = __float2half_rn(w[((size_t)oc * CIN + c) * 9 + kidx]);
    }
}

// ---------------- main kernel ----------------
// smem/CTA: [0] s_out4(32 u32)  [1024] A0,A1,A2 (16384 B each)
//           [50176] halo (368 slots x 160 B = 58880)   total 109056
//   -> 2 CTAs/SM. Epilogue reuses [1024..] as sO[128][132] f32 (67584 B).
#define SM_A0   1024
#define SM_HALO (SM_A0 + 3*16384)
#define SM_TOT  (SM_HALO + NSLOT*BSTRB)

__global__ __launch_bounds__(NTHR, 2) void conv_mma(float* __restrict__ out) {
    extern __shared__ char smem[];
    uint32_t* s_out4 = (uint32_t*)smem;
    const uint32_t sb = (uint32_t)__cvta_generic_to_shared(smem);

    const int t = threadIdx.x;
    const int w = t >> 5, lane = t & 31;
    const int g = lane >> 2, tig = lane & 3;
    const int ocHalf = w & 1, pxHalf = w >> 1;       // 2 x 2 warp grid, 64x64 tile
    const int base = blockIdx.x * NT;

    // pad-address of the tile's first pixel (halves) — reference for slots
    size_t pix0;
    {
        int bb = base / IMG, rr = base - bb * IMG;
        int y = rr / HW, xx = rr - y * HW;
        pix0 = (((size_t)bb * PADW + y) * PADW + xx) * CIN;
    }

    // per-thread B slot byte-offsets for the 8 'an' sub-tiles
    uint32_t bOff[8];
    #pragma unroll
    for (int an = 0; an < 8; an++) {
        int pg = base + pxHalf * 64 + an * 8 + g;        // global pixel id
        int bb = pg / IMG, rr = pg - bb * IMG;
        int y = rr / HW, xx = rr - y * HW;
        size_t pa = (((size_t)bb * PADW + y) * PADW + xx) * CIN;
        uint32_t slot = (uint32_t)((pa - pix0) >> 6);    // /CIN, max 249
        bOff[an] = SM_HALO + slot * BSTRB + tig * 8;
    }
    if (t < NT / 4) {
        int ng = base + t * 4;
        int bb = ng / IMG, rr = ng - bb * IMG;
        s_out4[t] = (uint32_t)bb * COUT * IMG + rr;
    }

    float d[4][8][4];                                 // [ao][an][j] = 128 regs
    #pragma unroll
    for (int ao = 0; ao < 4; ao++)
        #pragma unroll
        for (int an = 0; an < 8; an++)
            #pragma unroll
            for (int j = 0; j < 4; j++) d[ao][an][j] = 0.f;

    // stage A tap kidx into buffer buf (0..2)
    auto stageA = [&](int kidx, int buf) {
        const uint32_t abuf = sb + SM_A0 + buf * 16384;
        const __half* asrc = g_wt2 + kidx * 8192;
        #pragma unroll
        for (int it = 0; it < 8; it++) {
            int i = t + it * NTHR;                       // 1024 x 16B
            cp16(abuf + i * 16, asrc + i * 8);
        }
    };

    // stage the 368-slot B halo once (clamped at array end; clamped slots
    // are only ever read as dead taps of nonexistent pixels)
    {
        #pragma unroll
        for (int it = 0; it < 23; it++) {
            int i = t + it * NTHR;                       // 2944 x 16B
            int slot = i >> 3, c8 = i & 7;
            size_t off = pix0 + (size_t)slot * CIN + c8 * 8;
            if (off > XPAD_HALVES - 8) off = XPAD_HALVES - 8;
            cp16(sb + SM_HALO + slot * BSTRB + c8 * 16, g_xpad + off);
        }
    }
    stageA(0, 0); CP_COMMIT();        // group0 = halo + A0
    stageA(1, 1); CP_COMMIT();        // group1 = A1

    int cur = 0;
    #pragma unroll 3
    for (int kk = 0; kk < 9; kk++) {
        if (kk < 8) { CP_WAIT(1); } else { CP_WAIT(0); }
        __syncthreads();

        const char* sA = smem + SM_A0 + cur * 16384;
        const char* aBase = sA + (ocHalf * 4) * 512 + lane * 16;
        const uint32_t tapB = (uint32_t)((kk / 3) * PADW + (kk % 3)) * BSTRB;

        #pragma unroll
        for (int s = 0; s < 4; s++) {
            uint32_t a[4][4];
            #pragma unroll
            for (int ao = 0; ao < 4; ao++) {
                uint4 v = *(const uint4*)(aBase + s * 4096 + ao * 512);
                a[ao][0] = v.x; a[ao][1] = v.y; a[ao][2] = v.z; a[ao][3] = v.w;
            }
            uint32_t b0[8], b1[8];
            #pragma unroll
            for (int an = 0; an < 8; an++) {
                uint2 v2 = *(const uint2*)(smem + bOff[an] + tapB + s * 32);
                b0[an] = v2.x; b1[an] = v2.y;
            }
            #pragma unroll
            for (int ao = 0; ao < 4; ao++)
                #pragma unroll
                for (int an = 0; an < 8; an++)
                    mma16(d[ao][an], a[ao], b0[an], b1[an]);
        }

        // stage A(kk+2) into the buffer compute(kk-1) used; all warps are past
        // sync(kk) which follows their compute(kk-1) -> safe.
        if (kk < 7) {
            int nb = (cur == 0) ? 2 : cur - 1;   // (kk+2) % 3
            stageA(kk + 2, nb);
            CP_COMMIT();
        }
        cur = (cur == 2) ? 0 : cur + 1;
    }

    // epilogue: accums -> sO[oc][132] -> coalesced STG.128
    __syncthreads();
    float* sO = (float*)(smem + SM_A0);
    #pragma unroll
    for (int ao = 0; ao < 4; ao++)
        #pragma unroll
        for (int an = 0; an < 8; an++)
            #pragma unroll
            for (int j = 0; j < 4; j++) {
                int oc = ocHalf * 64 + ao * 16 + g + ((j >> 1) << 3);
                int px = pxHalf * 64 + an * 8 + 2 * tig + (j & 1);
                sO[oc * 132 + px] = d[ao][an][j];
            }
    __syncthreads();

    #pragma unroll
    for (int it = 0; it < 32; it++) {
        int i = t + it * NTHR;                           // 4096 float4
        int oc = i >> 5, q = i & 31;
        float4 v = *(const float4*)(sO + oc * 132 + q * 4);
        *(float4*)(out + (size_t)s_out4[q] + (size_t)oc * IMG) = v;
    }
}

extern "C" void kernel_launch(void* const* d_in, const int* in_sizes, int n_in,
                              void* d_out, int out_size) {
    const float* x = (const float*)d_in[0];
    const float* w = (const float*)d_in[1];
    float* out = (float*)d_out;

    k_prep<<<TGRID + (9 * COUT * CIN + PTHR - 1) / PTHR, PTHR>>>(x, w);

    cudaFuncSetAttribute(conv_mma, cudaFuncAttributeMaxDynamicSharedMemorySize, SM_TOT);
    conv_mma<<<NCTA, NTHR, SM_TOT>>>(out);
}

// round 15
// speedup vs baseline: 1.0279x; 1.0279x over previous
#include <cuda_runtime.h>
#include <cuda_fp16.h>
#include <cstdint>

// Conv2d 3x3 s1 p1: x[32,64,56,56] * w[128,64,3,3] -> out[32,128,56,56]
// FP16 implicit GEMM (fp32 accum), mma.sync m16n8k16. 64x64 warp tile.
// B halo staged once per CTA (368 slots, stride 160B, channel-permuted,
// conflict-free LDS.64). A taps cp.async triple-buffered. 2 CTAs/SM.
// This round: prep transpose writes vectorized to STG.128 (was scalar 2B).

#define B_    32
#define CIN   64
#define COUT  128
#define HW    56
#define PADW  58
#define IMG   (HW*HW)             // 3136
#define NPIX  (B_*IMG)            // 100352
#define NT    128                 // pixels per CTA
#define NCTA  (NPIX/NT)           // 784
#define BSTRB 160                 // bytes per halo slot row (128B data + pad)
#define NSLOT 368                 // staged halo slot rows (max read slot = 367)
#define NTHR  128
#define PTHR  256                 // prep threads
#define TGRID (PADW*B_)           // 1856 transpose blocks

__device__ __half g_xpad[(size_t)B_*PADW*PADW*CIN];  // fp16 NHWC padded, channel-permuted
__device__ __half g_wt2[9*COUT*CIN];                 // fragment-major fp16 weights

#define XPAD_HALVES ((size_t)B_*PADW*PADW*CIN)

static __device__ __forceinline__ void mma16(float* d, const uint32_t* a,
                                             uint32_t b0, uint32_t b1) {
    asm volatile("mma.sync.aligned.m16n8k16.row.col.f32.f16.f16.f32 "
                 "{%0,%1,%2,%3}, {%4,%5,%6,%7}, {%8,%9}, {%0,%1,%2,%3};"
                 : "+f"(d[0]), "+f"(d[1]), "+f"(d[2]), "+f"(d[3])
                 : "r"(a[0]), "r"(a[1]), "r"(a[2]), "r"(a[3]), "r"(b0), "r"(b1));
}
static __device__ __forceinline__ void cp16(uint32_t saddr, const void* g) {
    asm volatile("cp.async.cg.shared.global [%0], [%1], 16;" :: "r"(saddr), "l"(g));
}
#define CP_COMMIT() asm volatile("cp.async.commit_group;" ::: "memory")
#define CP_WAIT(n)  asm volatile("cp.async.wait_group %0;" :: "n"(n) : "memory")

// channel permutation: slot position p holds channel pi(p)
static __device__ __forceinline__ int chan_pi(int p) {
    int s = p >> 4, r = p & 15, tig = r >> 2, j = r & 3;
    return s * 16 + 2 * tig + (j & 1) + ((j >> 1) & 1) * 8;
}

// ---------------- fused prep kernel ----------------
__global__ void k_prep(const float* __restrict__ x, const float* __restrict__ w) {
    const int bid = blockIdx.x, t = threadIdx.x;
    if (bid < TGRID) {
        int yp = bid % PADW, b = bid / PADW;
        __half* dst = g_xpad + ((size_t)b * PADW + yp) * PADW * CIN;
        if (yp == 0 || yp == PADW - 1) {
            // vectorized zero row: 464 x 16B
            const uint4 z = make_uint4(0, 0, 0, 0);
            for (int i = t; i < PADW * CIN / 8; i += PTHR)
                *(uint4*)(dst + i * 8) = z;
            return;
        }
        __shared__ float s[CIN][HW + 1];
        int y = yp - 1;
        for (int i = t; i < CIN * HW; i += PTHR) {
            int c = i / HW, xx = i % HW;
            s[c][xx] = x[(((size_t)b * CIN + c) * HW + y) * HW + xx];
        }
        __syncthreads();
        if (t < 16) {                    // zero left/right halo columns, 16B each
            const uint4 z = make_uint4(0, 0, 0, 0);
            int side = t >> 3, q = t & 7;
            *(uint4*)(dst + (side ? (PADW - 1) * CIN : 0) + q * 8) = z;
        }
        // vectorized permuted write: 448 x half8 -> STG.128, coalesced
        for (int i = t; i < HW * CIN / 8; i += PTHR) {
            int px = i >> 3, po = (i & 7) * 8;
            __half h[8];
            #pragma unroll
            for (int m = 0; m < 8; m++)
                h[m] = __float2half_rn(s[chan_pi(po + m)][px]);
            *(uint4*)(dst + (px + 1) * CIN + po) = *(const uint4*)h;
        }
    } else {
        // per kidx: [s(4)][atom(8)][lane(32)][j(8 halves)] = 8192 halves
        // (A-side channel mapping unchanged: contraction order is preserved,
        //  only B's storage order is permuted.)
        int i = (bid - TGRID) * PTHR + t;
        if (i >= 9 * COUT * CIN) return;
        int kidx = i / 8192;
        int e    = i % 8192;
        int s    = e / 2048;
        int atom = (e / 256) & 7;
        int lane = (e >> 3) & 31;
        int j    = e & 7;
        int oc = atom * 16 + (lane >> 2) + ((j >> 1) & 1) * 8;
        int c  = s * 16 + 2 * (lane & 3) + (j & 1) + ((j >> 2) & 1) * 8;
        g_wt2[i] = __float2half_rn(w[((size_t)oc * CIN + c) * 9 + kidx]);
    }
}

// ---------------- main kernel (unchanged from round 14) ----------------
// smem/CTA: [0] s_out4(32 u32)  [1024] A0,A1,A2 (16384 B each)
//           [50176] halo (368 slots x 160 B = 58880)   total 109056
//   -> 2 CTAs/SM. Epilogue reuses [1024..] as sO[128][132] f32 (67584 B).
#define SM_A0   1024
#define SM_HALO (SM_A0 + 3*16384)
#define SM_TOT  (SM_HALO + NSLOT*BSTRB)

__global__ __launch_bounds__(NTHR, 2) void conv_mma(float* __restrict__ out) {
    extern __shared__ char smem[];
    uint32_t* s_out4 = (uint32_t*)smem;
    const uint32_t sb = (uint32_t)__cvta_generic_to_shared(smem);

    const int t = threadIdx.x;
    const int w = t >> 5, lane = t & 31;
    const int g = lane >> 2, tig = lane & 3;
    const int ocHalf = w & 1, pxHalf = w >> 1;       // 2 x 2 warp grid, 64x64 tile
    const int base = blockIdx.x * NT;

    // pad-address of the tile's first pixel (halves) — reference for slots
    size_t pix0;
    {
        int bb = base / IMG, rr = base - bb * IMG;
        int y = rr / HW, xx = rr - y * HW;
        pix0 = (((size_t)bb * PADW + y) * PADW + xx) * CIN;
    }

    // per-thread B slot byte-offsets for the 8 'an' sub-tiles
    uint32_t bOff[8];
    #pragma unroll
    for (int an = 0; an < 8; an++) {
        int pg = base + pxHalf * 64 + an * 8 + g;        // global pixel id
        int bb = pg / IMG, rr = pg - bb * IMG;
        int y = rr / HW, xx = rr - y * HW;
        size_t pa = (((size_t)bb * PADW + y) * PADW + xx) * CIN;
        uint32_t slot = (uint32_t)((pa - pix0) >> 6);    // /CIN, max 249
        bOff[an] = SM_HALO + slot * BSTRB + tig * 8;
    }
    if (t < NT / 4) {
        int ng = base + t * 4;
        int bb = ng / IMG, rr = ng - bb * IMG;
        s_out4[t] = (uint32_t)bb * COUT * IMG + rr;
    }

    float d[4][8][4];                                 // [ao][an][j] = 128 regs
    #pragma unroll
    for (int ao = 0; ao < 4; ao++)
        #pragma unroll
        for (int an = 0; an < 8; an++)
            #pragma unroll
            for (int j = 0; j < 4; j++) d[ao][an][j] = 0.f;

    // stage A tap kidx into buffer buf (0..2)
    auto stageA = [&](int kidx, int buf) {
        const uint32_t abuf = sb + SM_A0 + buf * 16384;
        const __half* asrc = g_wt2 + kidx * 8192;
        #pragma unroll
        for (int it = 0; it < 8; it++) {
            int i = t + it * NTHR;                       // 1024 x 16B
            cp16(abuf + i * 16, asrc + i * 8);
        }
    };

    // stage the 368-slot B halo once (clamped at array end; clamped slots
    // are only ever read as dead taps of nonexistent pixels)
    {
        #pragma unroll
        for (int it = 0; it < 23; it++) {
            int i = t + it * NTHR;                       // 2944 x 16B
            int slot = i >> 3, c8 = i & 7;
            size_t off = pix0 + (size_t)slot * CIN + c8 * 8;
            if (off > XPAD_HALVES - 8) off = XPAD_HALVES - 8;
            cp16(sb + SM_HALO + slot * BSTRB + c8 * 16, g_xpad + off);
        }
    }
    stageA(0, 0); CP_COMMIT();        // group0 = halo + A0
    stageA(1, 1); CP_COMMIT();        // group1 = A1

    int cur = 0;
    #pragma unroll 3
    for (int kk = 0; kk < 9; kk++) {
        if (kk < 8) { CP_WAIT(1); } else { CP_WAIT(0); }
        __syncthreads();

        const char* sA = smem + SM_A0 + cur * 16384;
        const char* aBase = sA + (ocHalf * 4) * 512 + lane * 16;
        const uint32_t tapB = (uint32_t)((kk / 3) * PADW + (kk % 3)) * BSTRB;

        #pragma unroll
        for (int s = 0; s < 4; s++) {
            uint32_t a[4][4];
            #pragma unroll
            for (int ao = 0; ao < 4; ao++) {
                uint4 v = *(const uint4*)(aBase + s * 4096 + ao * 512);
                a[ao][0] = v.x; a[ao][1] = v.y; a[ao][2] = v.z; a[ao][3] = v.w;
            }
            uint32_t b0[8], b1[8];
            #pragma unroll
            for (int an = 0; an < 8; an++) {
                uint2 v2 = *(const uint2*)(smem + bOff[an] + tapB + s * 32);
                b0[an] = v2.x; b1[an] = v2.y;
            }
            #pragma unroll
            for (int ao = 0; ao < 4; ao++)
                #pragma unroll
                for (int an = 0; an < 8; an++)
                    mma16(d[ao][an], a[ao], b0[an], b1[an]);
        }

        // stage A(kk+2) into the buffer compute(kk-1) used; all warps are past
        // sync(kk) which follows their compute(kk-1) -> safe.
        if (kk < 7) {
            int nb = (cur == 0) ? 2 : cur - 1;   // (kk+2) % 3
            stageA(kk + 2, nb);
            CP_COMMIT();
        }
        cur = (cur == 2) ? 0 : cur + 1;
    }

    // epilogue: accums -> sO[oc][132] -> coalesced STG.128
    __syncthreads();
    float* sO = (float*)(smem + SM_A0);
    #pragma unroll
    for (int ao = 0; ao < 4; ao++)
        #pragma unroll
        for (int an = 0; an < 8; an++)
            #pragma unroll
            for (int j = 0; j < 4; j++) {
                int oc = ocHalf * 64 + ao * 16 + g + ((j >> 1) << 3);
                int px = pxHalf * 64 + an * 8 + 2 * tig + (j & 1);
                sO[oc * 132 + px] = d[ao][an][j];
            }
    __syncthreads();

    #pragma unroll
    for (int it = 0; it < 32; it++) {
        int i = t + it * NTHR;                           // 4096 float4
        int oc = i >> 5, q = i & 31;
        float4 v = *(const float4*)(sO + oc * 132 + q * 4);
        *(float4*)(out + (size_t)s_out4[q] + (size_t)oc * IMG) = v;
    }
}

extern "C" void kernel_launch(void* const* d_in, const int* in_sizes, int n_in,
                              void* d_out, int out_size) {
    const float* x = (const float*)d_in[0];
    const float* w = (const float*)d_in[1];
    float* out = (float*)d_out;

    k_prep<<<TGRID + (9 * COUT * CIN + PTHR - 1) / PTHR, PTHR>>>(x, w);

    cudaFuncSetAttribute(conv_mma, cudaFuncAttributeMaxDynamicSharedMemorySize, SM_TOT);
    conv_mma<<<NCTA, NTHR, SM_TOT>>>(out);
}

// round 16
// speedup vs baseline: 1.1713x; 1.1395x over previous
#include <cuda_runtime.h>
#include <cuda_fp16.h>
#include <cstdint>

// Conv2d 3x3 s1 p1: x[32,64,56,56] * w[128,64,3,3] -> out[32,128,56,56]
// FP16 implicit GEMM (fp32 accum), mma.sync m16n8k16.
// CTA = 128oc x 64px, 4 warps of 64x32, 3 CTAs/SM (12 warps/SM).
// B halo staged once per CTA (192 slots, stride 160B, channel-permuted,
// conflict-free LDS.64). A taps cp.async double-buffered.

#define B_    32
#define CIN   64
#define COUT  128
#define HW    56
#define PADW  58
#define IMG   (HW*HW)             // 3136
#define NPIX  (B_*IMG)            // 100352
#define NT    64                  // pixels per CTA (64 | 3136: no batch crossing)
#define NCTA  (NPIX/NT)           // 1568
#define BSTRB 160                 // bytes per halo slot row (128B data + pad)
#define NSLOT 192                 // staged halo slot rows (max read slot = 183)
#define NTHR  128
#define PTHR  256                 // prep threads
#define TGRID (PADW*B_)           // 1856 transpose blocks

__device__ __half g_xpad[(size_t)B_*PADW*PADW*CIN];  // fp16 NHWC padded, channel-permuted
__device__ __half g_wt2[9*COUT*CIN];                 // fragment-major fp16 weights

#define XPAD_HALVES ((size_t)B_*PADW*PADW*CIN)

static __device__ __forceinline__ void mma16(float* d, const uint32_t* a,
                                             uint32_t b0, uint32_t b1) {
    asm volatile("mma.sync.aligned.m16n8k16.row.col.f32.f16.f16.f32 "
                 "{%0,%1,%2,%3}, {%4,%5,%6,%7}, {%8,%9}, {%0,%1,%2,%3};"
                 : "+f"(d[0]), "+f"(d[1]), "+f"(d[2]), "+f"(d[3])
                 : "r"(a[0]), "r"(a[1]), "r"(a[2]), "r"(a[3]), "r"(b0), "r"(b1));
}
static __device__ __forceinline__ void cp16(uint32_t saddr, const void* g) {
    asm volatile("cp.async.cg.shared.global [%0], [%1], 16;" :: "r"(saddr), "l"(g));
}
#define CP_COMMIT() asm volatile("cp.async.commit_group;" ::: "memory")
#define CP_WAIT(n)  asm volatile("cp.async.wait_group %0;" :: "n"(n) : "memory")

// channel permutation: slot position p holds channel pi(p)
static __device__ __forceinline__ int chan_pi(int p) {
    int s = p >> 4, r = p & 15, tig = r >> 2, j = r & 3;
    return s * 16 + 2 * tig + (j & 1) + ((j >> 1) & 1) * 8;
}

// ---------------- fused prep kernel ----------------
__global__ void k_prep(const float* __restrict__ x, const float* __restrict__ w) {
    const int bid = blockIdx.x, t = threadIdx.x;
    if (bid < TGRID) {
        int yp = bid % PADW, b = bid / PADW;
        __half* dst = g_xpad + ((size_t)b * PADW + yp) * PADW * CIN;
        if (yp == 0 || yp == PADW - 1) {
            const uint4 z = make_uint4(0, 0, 0, 0);
            for (int i = t; i < PADW * CIN / 8; i += PTHR)
                *(uint4*)(dst + i * 8) = z;
            return;
        }
        __shared__ float s[CIN][60];                 // stride 60: 16B-aligned rows
        int y = yp - 1;
        // vectorized loads: 896 float4 (14 per channel row)
        for (int i = t; i < CIN * (HW / 4); i += PTHR) {
            int c = i / 14, xq = i % 14;
            float4 v = *(const float4*)(x + (((size_t)b * CIN + c) * HW + y) * HW + xq * 4);
            *(float4*)&s[c][xq * 4] = v;
        }
        __syncthreads();
        if (t < 16) {                    // zero left/right halo columns, 16B each
            const uint4 z = make_uint4(0, 0, 0, 0);
            int side = t >> 3, q = t & 7;
            *(uint4*)(dst + (side ? (PADW - 1) * CIN : 0) + q * 8) = z;
        }
        // vectorized permuted write: 448 x half8 -> STG.128, coalesced
        for (int i = t; i < HW * CIN / 8; i += PTHR) {
            int px = i >> 3, po = (i & 7) * 8;
            __half h[8];
            #pragma unroll
            for (int m = 0; m < 8; m++)
                h[m] = __float2half_rn(s[chan_pi(po + m)][px]);
            *(uint4*)(dst + (px + 1) * CIN + po) = *(const uint4*)h;
        }
    } else {
        // per kidx: [s(4)][atom(8)][lane(32)][j(8 halves)] = 8192 halves
        int i = (bid - TGRID) * PTHR + t;
        if (i >= 9 * COUT * CIN) return;
        int kidx = i / 8192;
        int e    = i % 8192;
        int s    = e / 2048;
        int atom = (e / 256) & 7;
        int lane = (e >> 3) & 31;
        int j    = e & 7;
        int oc = atom * 16 + (lane >> 2) + ((j >> 1) & 1) * 8;
        int c  = s * 16 + 2 * (lane & 3) + (j & 1) + ((j >> 2) & 1) * 8;
        g_wt2[i] = __float2half_rn(w[((size_t)oc * CIN + c) * 9 + kidx]);
    }
}

// ---------------- main kernel ----------------
// smem/CTA: [0] s_out4(16 u32)  [1024] A0,A1 (16384 B each)
//           [33792] halo (192 slots x 160 B = 30720)   total 64512
//   -> 3 CTAs/SM (193536 B). Epilogue reuses [1024..] as sO[128][68] f32 (34816 B).
#define SM_A0   1024
#define SM_HALO (SM_A0 + 2*16384)
#define SM_TOT  (SM_HALO + NSLOT*BSTRB)

__global__ __launch_bounds__(NTHR, 3) void conv_mma(float* __restrict__ out) {
    extern __shared__ char smem[];
    uint32_t* s_out4 = (uint32_t*)smem;
    const uint32_t sb = (uint32_t)__cvta_generic_to_shared(smem);

    const int t = threadIdx.x;
    const int w = t >> 5, lane = t & 31;
    const int g = lane >> 2, tig = lane & 3;
    const int ocHalf = w & 1, pxHalf = w >> 1;       // 2 x 2 warp grid, 64x32 tiles
    const int base = blockIdx.x * NT;

    // pad-address of the tile's first pixel (halves) — reference for slots
    size_t pix0;
    {
        int bb = base / IMG, rr = base - bb * IMG;
        int y = rr / HW, xx = rr - y * HW;
        pix0 = (((size_t)bb * PADW + y) * PADW + xx) * CIN;
    }

    // per-thread B slot byte-offsets for the 4 'an' sub-tiles
    uint32_t bOff[4];
    #pragma unroll
    for (int an = 0; an < 4; an++) {
        int pg = base + pxHalf * 32 + an * 8 + g;        // global pixel id
        int bb = pg / IMG, rr = pg - bb * IMG;
        int y = rr / HW, xx = rr - y * HW;
        size_t pa = (((size_t)bb * PADW + y) * PADW + xx) * CIN;
        uint32_t slot = (uint32_t)((pa - pix0) >> 6);    // /CIN, max 65
        bOff[an] = SM_HALO + slot * BSTRB + tig * 8;
    }
    if (t < NT / 4) {
        int ng = base + t * 4;
        int bb = ng / IMG, rr = ng - bb * IMG;
        s_out4[t] = (uint32_t)bb * COUT * IMG + rr;
    }

    float d[4][4][4];                                 // [ao][an][j] = 64 regs
    #pragma unroll
    for (int ao = 0; ao < 4; ao++)
        #pragma unroll
        for (int an = 0; an < 4; an++)
            #pragma unroll
            for (int j = 0; j < 4; j++) d[ao][an][j] = 0.f;

    // stage A tap kidx into buffer buf (0/1)
    auto stageA = [&](int kidx, int buf) {
        const uint32_t abuf = sb + SM_A0 + buf * 16384;
        const __half* asrc = g_wt2 + kidx * 8192;
        #pragma unroll
        for (int it = 0; it < 8; it++) {
            int i = t + it * NTHR;                       // 1024 x 16B
            cp16(abuf + i * 16, asrc + i * 8);
        }
    };

    // stage the 192-slot B halo once (clamped at array end; clamped slots
    // are only ever read as dead taps of nonexistent pixels)
    {
        #pragma unroll
        for (int it = 0; it < 12; it++) {
            int i = t + it * NTHR;                       // 1536 x 16B
            int slot = i >> 3, c8 = i & 7;
            size_t off = pix0 + (size_t)slot * CIN + c8 * 8;
            if (off > XPAD_HALVES - 8) off = XPAD_HALVES - 8;
            cp16(sb + SM_HALO + slot * BSTRB + c8 * 16, g_xpad + off);
        }
    }
    stageA(0, 0); CP_COMMIT();        // g0 = halo + A0

    #pragma unroll 3
    for (int kk = 0; kk < 9; kk++) {
        CP_WAIT(0);                    // g(kk) committed one full iter ago
        __syncthreads();               // all warps past compute(kk-1)
        if (kk < 8) { stageA(kk + 1, (kk + 1) & 1); CP_COMMIT(); }

        const char* sA = smem + SM_A0 + (kk & 1) * 16384;
        const char* aBase = sA + (ocHalf * 4) * 512 + lane * 16;
        const uint32_t tapB = (uint32_t)((kk / 3) * PADW + (kk % 3)) * BSTRB;

        #pragma unroll
        for (int s = 0; s < 4; s++) {
            uint32_t a[4][4];
            #pragma unroll
            for (int ao = 0; ao < 4; ao++) {
                uint4 v = *(const uint4*)(aBase + s * 4096 + ao * 512);
                a[ao][0] = v.x; a[ao][1] = v.y; a[ao][2] = v.z; a[ao][3] = v.w;
            }
            uint32_t b0[4], b1[4];
            #pragma unroll
            for (int an = 0; an < 4; an++) {
                uint2 v2 = *(const uint2*)(smem + bOff[an] + tapB + s * 32);
                b0[an] = v2.x; b1[an] = v2.y;
            }
            #pragma unroll
            for (int ao = 0; ao < 4; ao++)
                #pragma unroll
                for (int an = 0; an < 4; an++)
                    mma16(d[ao][an], a[ao], b0[an], b1[an]);
        }
    }

    // epilogue: accums -> sO[oc][68] -> coalesced STG.128
    __syncthreads();
    float* sO = (float*)(smem + SM_A0);
    #pragma unroll
    for (int ao = 0; ao < 4; ao++)
        #pragma unroll
        for (int an = 0; an < 4; an++)
            #pragma unroll
            for (int j = 0; j < 4; j++) {
                int oc = ocHalf * 64 + ao * 16 + g + ((j >> 1) << 3);
                int px = pxHalf * 32 + an * 8 + 2 * tig + (j & 1);
                sO[oc * 68 + px] = d[ao][an][j];
            }
    __syncthreads();

    #pragma unroll
    for (int it = 0; it < 16; it++) {
        int i = t + it * NTHR;                           // 2048 float4
        int oc = i >> 4, q = i & 15;
        float4 v = *(const float4*)(sO + oc * 68 + q * 4);
        *(float4*)(out + (size_t)s_out4[q] + (size_t)oc * IMG) = v;
    }
}

extern "C" void kernel_launch(void* const* d_in, const int* in_sizes, int n_in,
                              void* d_out, int out_size) {
    const float* x = (const float*)d_in[0];
    const float* w = (const float*)d_in[1];
    float* out = (float*)d_out;

    k_prep<<<TGRID + (9 * COUT * CIN + PTHR - 1) / PTHR, PTHR>>>(x, w);

    cudaFuncSetAttribute(conv_mma, cudaFuncAttributeMaxDynamicSharedMemorySize, SM_TOT);
    conv_mma<<<NCTA, NTHR, SM_TOT>>>(out);
}